// round 15
// baseline (speedup 1.0000x reference)
#include <cuda_runtime.h>
#include <cuda_fp16.h>
#include <cstdint>

#define H 4096
#define INF 4096
#define OUTF 4096
#define KRED 256
#define NRED 16

__device__ __half g_xs[H * KRED];
__device__ __half g_wsT[OUTF * KRED];

// ---------------------------------------------------------------------------
// Fused reduction (proven ~6.8 TB/s). Streamed inputs with evict-first.
// ---------------------------------------------------------------------------
__device__ __forceinline__ float4 ldcs4(const float4* p) {
    float4 v;
    asm volatile("ld.global.cs.v4.f32 {%0,%1,%2,%3}, [%4];"
                 : "=f"(v.x), "=f"(v.y), "=f"(v.z), "=f"(v.w) : "l"(p));
    return v;
}

__global__ void __launch_bounds__(256) lin_reduce(const float* __restrict__ x,
                                                  const float* __restrict__ w) {
    int b = blockIdx.x;
    const float* src;
    __half* dst;
    if (b < 1024) { src = x; dst = g_xs; }
    else          { src = w; dst = g_wsT; b -= 1024; }
    const int row = b * 4 + (threadIdx.x >> 6);
    const int p = (threadIdx.x & 63) * 4;
    const float4* s = (const float4*)(src + (size_t)row * INF + p);
    float4 a0 = make_float4(0.f, 0.f, 0.f, 0.f);
    float4 a1 = make_float4(0.f, 0.f, 0.f, 0.f);
#pragma unroll
    for (int v = 0; v < NRED; v += 2) {
        float4 t0 = ldcs4(s + v * (KRED / 4));
        float4 t1 = ldcs4(s + (v + 1) * (KRED / 4));
        a0.x += t0.x; a0.y += t0.y; a0.z += t0.z; a0.w += t0.w;
        a1.x += t1.x; a1.y += t1.y; a1.z += t1.z; a1.w += t1.w;
    }
    a0.x += a1.x; a0.y += a1.y; a0.z += a1.z; a0.w += a1.w;
    __half2 lo = __floats2half2_rn(a0.x, a0.y);
    __half2 hi = __floats2half2_rn(a0.z, a0.w);
    uint2 pk = make_uint2(*(uint32_t*)&lo, *(uint32_t*)&hi);
    *(uint2*)(dst + (size_t)row * KRED + p) = pk;
}

// ---------------------------------------------------------------------------
// GEMM: CTA 128x128, 256 threads, 8 warps 4x2 (warp tile 32x64).
// KC=32, 8 chunks, 4-stage cp.async pipeline, wait_group 2. 2 CTAs/SM.
// ---------------------------------------------------------------------------
#define BM 128
#define BN 128
#define KC 32
#define NCHUNK (KRED / KC)              // 8
#define LDSTR 40                        // halves per row (80 B), conflict-free
#define A_BUF (BM * LDSTR)              // 5120 halves
#define B_BUF (BN * LDSTR)              // 5120 halves
#define STAGE_H (A_BUF + B_BUF)         // 10240 halves
#define STAGE_B (STAGE_H * 2)           // 20480 B
#define SMEM_BYTES (4 * STAGE_B + 512)  // 82432 B -> 2 CTAs/SM

__device__ __forceinline__ void mma_f16(float* d, const uint32_t* a, const uint32_t* b) {
    asm volatile(
        "mma.sync.aligned.m16n8k16.row.col.f32.f16.f16.f32 "
        "{%0,%1,%2,%3}, {%4,%5,%6,%7}, {%8,%9}, {%0,%1,%2,%3};\n"
        : "+f"(d[0]), "+f"(d[1]), "+f"(d[2]), "+f"(d[3])
        : "r"(a[0]), "r"(a[1]), "r"(a[2]), "r"(a[3]),
          "r"(b[0]), "r"(b[1]));
}
__device__ __forceinline__ void cp16(uint32_t dst, const void* src) {
    asm volatile("cp.async.cg.shared.global [%0], [%1], 16;"
                 :: "r"(dst), "l"(src) : "memory");
}
__device__ __forceinline__ void ldm_x4(uint32_t& r0, uint32_t& r1, uint32_t& r2,
                                       uint32_t& r3, uint32_t addr) {
    asm volatile("ldmatrix.sync.aligned.m8n8.x4.shared.b16 {%0,%1,%2,%3}, [%4];"
                 : "=r"(r0), "=r"(r1), "=r"(r2), "=r"(r3) : "r"(addr));
}

__global__ void __launch_bounds__(256, 2)
lin_gemm(const float* __restrict__ bias, float* __restrict__ out) {
    extern __shared__ __half smh[];
    float* s_bias = (float*)(smh + 4 * STAGE_H);

    const int tid = threadIdx.x;
    const int warp = tid >> 5;
    const int lane = tid & 31;
    const int wm = warp >> 1;            // 0..3 -> 32-row slab
    const int wn = warp & 1;             // 0..1 -> 64-col slab
    const int g = lane >> 2;
    const int t = lane & 3;
    const int m0 = blockIdx.y * BM;
    const int n0 = blockIdx.x * BN;

    if (tid < 128) s_bias[tid] = bias[n0 + tid];

    // cooperative load: 4 threads per 32-half row; 64 rows per pass; 2 passes each
    const int lrow = tid >> 2;           // 0..63
    const int lch = (tid & 3) * 8;       // half offset in row

    const uint32_t smem0 = (uint32_t)__cvta_generic_to_shared(smh);
    const uint32_t aDst0 = smem0 + (lrow * LDSTR + lch) * 2;
    const uint32_t bDst0 = smem0 + (A_BUF + lrow * LDSTR + lch) * 2;
    const __half* aSrc = g_xs + (size_t)(m0 + lrow) * KRED + lch;
    const __half* bSrc = g_wsT + (size_t)(n0 + lrow) * KRED + lch;

    // ldmatrix lane offsets
    const int aRow = (lane & 7) + ((lane >> 3) & 1) * 8;
    const int aK = (lane >> 4) * 8;
    const uint32_t aLdmOff = ((wm * 32 + aRow) * LDSTR + aK) * 2;
    const int bRow = (lane & 7) + ((lane >> 4) & 1) * 8;
    const int bK = ((lane >> 3) & 1) * 8;
    const uint32_t bLdmOff = (uint32_t)(A_BUF * 2) + ((wn * 64 + bRow) * LDSTR + bK) * 2;

    float acc[2][8][4];
#pragma unroll
    for (int mt = 0; mt < 2; mt++)
#pragma unroll
        for (int nt = 0; nt < 8; nt++)
#pragma unroll
            for (int i = 0; i < 4; i++) acc[mt][nt][i] = 0.f;

    // prologue: prefetch chunks 0,1,2 into stages 0,1,2
#pragma unroll
    for (int pc = 0; pc < 3; pc++) {
        const uint32_t so = pc * STAGE_B;
        const int kc = pc * KC;
#pragma unroll
        for (int r = 0; r < 2; r++) {
            cp16(aDst0 + so + r * 64 * LDSTR * 2, aSrc + (size_t)r * 64 * KRED + kc);
            cp16(bDst0 + so + r * 64 * LDSTR * 2, bSrc + (size_t)r * 64 * KRED + kc);
        }
        asm volatile("cp.async.commit_group;" ::: "memory");
    }

#pragma unroll
    for (int c = 0; c < NCHUNK; c++) {
        // ensure chunk c's copy is complete (keep up to 2 newer in flight)
        if (c < NCHUNK - 2)      asm volatile("cp.async.wait_group 2;" ::: "memory");
        else if (c < NCHUNK - 1) asm volatile("cp.async.wait_group 1;" ::: "memory");
        else                     asm volatile("cp.async.wait_group 0;" ::: "memory");
        __syncthreads();

        if (c + 3 < NCHUNK) {
            const uint32_t so = ((c + 3) & 3) * STAGE_B;
            const int kc = (c + 3) * KC;
#pragma unroll
            for (int r = 0; r < 2; r++) {
                cp16(aDst0 + so + r * 64 * LDSTR * 2, aSrc + (size_t)r * 64 * KRED + kc);
                cp16(bDst0 + so + r * 64 * LDSTR * 2, bSrc + (size_t)r * 64 * KRED + kc);
            }
            asm volatile("cp.async.commit_group;" ::: "memory");
        }

        const uint32_t stageBase = smem0 + (c & 3) * STAGE_B;
        const uint32_t aAddr = stageBase + aLdmOff;
        const uint32_t bAddr = stageBase + bLdmOff;

#pragma unroll
        for (int s = 0; s < KC / 16; s++) {      // 2 k16 steps
            const int kkB = s * 16 * 2;
            uint32_t a[2][4], b[8][2];
#pragma unroll
            for (int mt = 0; mt < 2; mt++)
                ldm_x4(a[mt][0], a[mt][1], a[mt][2], a[mt][3],
                       aAddr + mt * 16 * LDSTR * 2 + kkB);
#pragma unroll
            for (int np = 0; np < 4; np++)
                ldm_x4(b[2 * np][0], b[2 * np][1], b[2 * np + 1][0], b[2 * np + 1][1],
                       bAddr + np * 16 * LDSTR * 2 + kkB);
#pragma unroll
            for (int mt = 0; mt < 2; mt++)
#pragma unroll
                for (int nt = 0; nt < 8; nt++)
                    mma_f16(acc[mt][nt], a[mt], b[nt]);
        }
    }

    // Epilogue: bias + float2 stores
#pragma unroll
    for (int mt = 0; mt < 2; mt++) {
        const int r0 = m0 + wm * 32 + mt * 16 + g;
#pragma unroll
        for (int nt = 0; nt < 8; nt++) {
            const int col = wn * 64 + nt * 8 + 2 * t;
            const float b0 = s_bias[col], b1 = s_bias[col + 1];
            float2 v0 = make_float2(acc[mt][nt][0] + b0, acc[mt][nt][1] + b1);
            float2 v1 = make_float2(acc[mt][nt][2] + b0, acc[mt][nt][3] + b1);
            *(float2*)&out[(size_t)r0 * OUTF + n0 + col] = v0;
            *(float2*)&out[(size_t)(r0 + 8) * OUTF + n0 + col] = v1;
        }
    }
}

extern "C" void kernel_launch(void* const* d_in, const int* in_sizes, int n_in,
                              void* d_out, int out_size) {
    const float* x = (const float*)d_in[0];
    const float* w = (const float*)d_in[1];
    const float* bias = (const float*)d_in[2];
    float* out = (float*)d_out;

    cudaFuncSetAttribute(lin_gemm, cudaFuncAttributeMaxDynamicSharedMemorySize, SMEM_BYTES);

    lin_reduce<<<2048, 256>>>(x, w);
    dim3 grid(OUTF / BN, H / BM);   // (32, 32)
    lin_gemm<<<grid, 256, SMEM_BYTES>>>(bias, out);
}